// round 5
// baseline (speedup 1.0000x reference)
#include <cuda_runtime.h>
#include <math.h>

// Batched SPD projection: per 64x64 real matrix A,
//   A = Q T Q^H  (Hessenberg + complex single-shift QR),
//   F = f(T) by Parlett with f(w) = |w| + eps*min|w|,
//   M = Q F Q^H,  out = 0.5*(Re(M) + Re(M)^T).

#define N 64
#define LDH 65
#define ULPF 1.1920929e-7f
#define MAXSWEEPS 1920

__device__ __forceinline__ float2 cadd(float2 a, float2 b) { return make_float2(a.x + b.x, a.y + b.y); }
__device__ __forceinline__ float2 csub(float2 a, float2 b) { return make_float2(a.x - b.x, a.y - b.y); }
__device__ __forceinline__ float2 cmul(float2 a, float2 b) {
    return make_float2(a.x * b.x - a.y * b.y, a.x * b.y + a.y * b.x);
}
__device__ __forceinline__ float cabs1(float2 a) { return fabsf(a.x) + fabsf(a.y); }
__device__ __forceinline__ float cabs2f(float2 a) { return a.x * a.x + a.y * a.y; }

__global__ void __launch_bounds__(64, 2)
spd_project_kernel(const float* __restrict__ X, float* __restrict__ OUT, int nmat)
{
    extern __shared__ float2 sm[];
    float2* H = sm;                 // Hessenberg -> T -> reused as G = Q*F
    float2* Q = sm + N * LDH;       // accumulated similarity
    float2* F = sm + 2 * N * LDH;   // f(T); later .x reused for Re(M)

    __shared__ float s_v[N];
    __shared__ float s_red[N];
    __shared__ int s_hi, s_lo, s_done;
    __shared__ float2 s_sigma, s_s;
    __shared__ float s_c;

    const int tid = threadIdx.x;
    const int g = blockIdx.x;
    if (g >= nmat) return;
    const float* A = X + (size_t)g * (N * N);
    float* Og = OUT + (size_t)g * (N * N);

    // ---------------- load A, Q = I ----------------
    for (int idx = tid; idx < N * N; idx += 64) {
        int i = idx >> 6, j = idx & 63;
        H[i * LDH + j] = make_float2(A[idx], 0.f);
        Q[i * LDH + j] = make_float2((i == j) ? 1.f : 0.f, 0.f);
    }
    __syncthreads();

    // ---------------- Hessenberg reduction (real; .y stays 0) ----------------
    for (int k = 0; k < N - 2; k++) {
        const int m = N - 1 - k;
        float t = 0.f;
        int row = k + 2 + tid;
        if (row < N) { float h = H[row * LDH + k].x; t = h * h; }
        s_red[tid] = t;
        __syncthreads();
        for (int off = 32; off >= 1; off >>= 1) {
            if (tid < off) s_red[tid] += s_red[tid + off];
            __syncthreads();
        }
        const float sigma = s_red[0];
        const float x0 = H[(k + 1) * LDH + k].x;
        float beta = 0.f, inv_v0 = 0.f;
        if (sigma > 0.f) {
            float mu = sqrtf(x0 * x0 + sigma);
            float v0 = (x0 <= 0.f) ? (x0 - mu) : (-sigma / (x0 + mu));
            beta = 2.f * v0 * v0 / (sigma + v0 * v0);
            inv_v0 = 1.f / v0;
        }
        if (beta != 0.f) {  // uniform across threads
            if (tid == 0) s_v[0] = 1.f;
            if (tid >= 1 && tid < m) s_v[tid] = H[(k + 1 + tid) * LDH + k].x * inv_v0;
            __syncthreads();
            // left: rows k+1.., one column per thread
            {
                int j = k + tid;
                if (j < N) {
                    float w = 0.f;
                    for (int i = 0; i < m; i++) w += s_v[i] * H[(k + 1 + i) * LDH + j].x;
                    w *= beta;
                    for (int i = 0; i < m; i++) H[(k + 1 + i) * LDH + j].x -= s_v[i] * w;
                }
            }
            __syncthreads();
            // right on H and Q, one row per thread
            {
                int i = tid;
                float w = 0.f;
                for (int l = 0; l < m; l++) w += H[i * LDH + k + 1 + l].x * s_v[l];
                w *= beta;
                for (int l = 0; l < m; l++) H[i * LDH + k + 1 + l].x -= w * s_v[l];
                float wq = 0.f;
                for (int l = 0; l < m; l++) wq += Q[i * LDH + k + 1 + l].x * s_v[l];
                wq *= beta;
                for (int l = 0; l < m; l++) Q[i * LDH + k + 1 + l].x -= wq * s_v[l];
            }
            __syncthreads();
        }
        if (tid >= k + 2 && tid < N) H[tid * LDH + k] = make_float2(0.f, 0.f);
        __syncthreads();
    }

    // ---------------- complex single-shift QR with deflation ----------------
    if (tid == 0) { s_hi = N - 1; }
    int its = 0, totit = 0;  // meaningful on thread 0 only
    __syncthreads();

    while (true) {
        if (tid == 0) {
            int hi = s_hi;
            while (hi > 0) {
                float sub = cabs1(H[hi * LDH + hi - 1]);
                float d = cabs1(H[(hi - 1) * LDH + hi - 1]) + cabs1(H[hi * LDH + hi]);
                if (sub <= ULPF * d + 1e-30f) {
                    H[hi * LDH + hi - 1] = make_float2(0.f, 0.f);
                    hi--; its = 0;
                } else break;
            }
            s_hi = hi;
            if (hi == 0 || totit >= MAXSWEEPS) {
                s_done = 1;
            } else {
                s_done = 0; totit++; its++;
                int lo = hi;
                while (lo > 0) {
                    float sub = cabs1(H[lo * LDH + lo - 1]);
                    float d = cabs1(H[(lo - 1) * LDH + lo - 1]) + cabs1(H[lo * LDH + lo]);
                    if (sub <= ULPF * d + 1e-30f) {
                        H[lo * LDH + lo - 1] = make_float2(0.f, 0.f);
                        break;
                    }
                    lo--;
                }
                s_lo = lo;
                float2 sig;
                if ((its % 10) == 0) {  // exceptional shift
                    sig = H[hi * LDH + hi];
                    sig.x += 0.75f * cabs1(H[hi * LDH + hi - 1]);
                } else {                // Wilkinson shift from trailing 2x2
                    float2 a = H[(hi - 1) * LDH + hi - 1], b = H[(hi - 1) * LDH + hi];
                    float2 cc = H[hi * LDH + hi - 1],      d2 = H[hi * LDH + hi];
                    float2 tr = make_float2(0.5f * (a.x + d2.x), 0.5f * (a.y + d2.y));
                    float2 u = make_float2(0.5f * (a.x - d2.x), 0.5f * (a.y - d2.y));
                    float2 disc = cadd(cmul(u, u), cmul(b, cc));
                    float mm = sqrtf(disc.x * disc.x + disc.y * disc.y);
                    float re = sqrtf(fmaxf(0.5f * (mm + disc.x), 0.f));
                    float im = sqrtf(fmaxf(0.5f * (mm - disc.x), 0.f));
                    im = copysignf(im, disc.y);
                    float2 sq = make_float2(re, im);
                    float2 e1 = cadd(tr, sq), e2 = csub(tr, sq);
                    sig = (cabs2f(csub(e1, d2)) < cabs2f(csub(e2, d2))) ? e1 : e2;
                }
                s_sigma = sig;
            }
        }
        __syncthreads();
        if (s_done) break;
        const int lo = s_lo, hi = s_hi;
        const float2 sig = s_sigma;

        // implicit single-shift bulge chase over [lo..hi]
        for (int k = lo; k < hi; k++) {
            if (tid == 0) {
                float2 f, gg;
                if (k == lo) { f = csub(H[lo * LDH + lo], sig); gg = H[(lo + 1) * LDH + lo]; }
                else         { f = H[k * LDH + k - 1];          gg = H[(k + 1) * LDH + k - 1]; }
                float c; float2 s;
                float ag = cabs2f(gg), af = cabs2f(f);
                if (ag == 0.f) {
                    c = 1.f; s = make_float2(0.f, 0.f);
                } else if (af == 0.f) {
                    c = 0.f;
                    float ginv = rsqrtf(ag);
                    s = make_float2(gg.x * ginv, -gg.y * ginv);  // conj(g)/|g|
                    if (k > lo) H[k * LDH + k - 1] = make_float2(sqrtf(ag), 0.f);
                } else {
                    float d = sqrtf(af + ag);
                    float fa = sqrtf(af);
                    c = fa / d;
                    float sc = 1.f / (fa * d);
                    s = make_float2((f.x * gg.x + f.y * gg.y) * sc,
                                    (f.y * gg.x - f.x * gg.y) * sc);  // (f/|f|)*conj(g)/d
                    if (k > lo) {
                        float rsc = d / fa;
                        H[k * LDH + k - 1] = make_float2(f.x * rsc, f.y * rsc);
                    }
                }
                if (k > lo) H[(k + 1) * LDH + k - 1] = make_float2(0.f, 0.f);
                s_c = c; s_s = s;
            }
            __syncthreads();
            const float c = s_c; const float2 s = s_s;
            // left: rows k,k+1 ; one column per thread, j >= k
            {
                int j = k + tid;
                if (j < N) {
                    float2 a = H[k * LDH + j], b = H[(k + 1) * LDH + j];
                    H[k * LDH + j]       = make_float2(c * a.x + s.x * b.x - s.y * b.y,
                                                       c * a.y + s.x * b.y + s.y * b.x);
                    H[(k + 1) * LDH + j] = make_float2(c * b.x - (s.x * a.x + s.y * a.y),
                                                       c * b.y - (s.x * a.y - s.y * a.x));
                }
            }
            __syncthreads();
            // right: cols k,k+1 on H (rows 0..min(k+2,hi)) and on Q (all rows)
            {
                int i = tid;
                int ilim = min(k + 2, hi);
                if (i <= ilim) {
                    float2 a = H[i * LDH + k], b = H[i * LDH + k + 1];
                    H[i * LDH + k]     = make_float2(c * a.x + s.x * b.x + s.y * b.y,
                                                     c * a.y + s.x * b.y - s.y * b.x);
                    H[i * LDH + k + 1] = make_float2(c * b.x - (s.x * a.x - s.y * a.y),
                                                     c * b.y - (s.x * a.y + s.y * a.x));
                }
                float2 qa = Q[i * LDH + k], qb = Q[i * LDH + k + 1];
                Q[i * LDH + k]     = make_float2(c * qa.x + s.x * qb.x + s.y * qb.y,
                                                 c * qa.y + s.x * qb.y - s.y * qb.x);
                Q[i * LDH + k + 1] = make_float2(c * qb.x - (s.x * qa.x - s.y * qa.y),
                                                 c * qb.y - (s.x * qa.y + s.y * qa.x));
            }
            __syncthreads();
        }
    }

    // ---------------- lam = |w| + eps*min|w| ----------------
    {
        float2 w = H[tid * LDH + tid];
        float a = sqrtf(w.x * w.x + w.y * w.y);
        s_red[tid] = a;
        __syncthreads();
        for (int off = 32; off >= 1; off >>= 1) {
            if (tid < off) s_red[tid] = fminf(s_red[tid], s_red[tid + off]);
            __syncthreads();
        }
        float amin = s_red[0];
        s_v[tid] = a + 1e-6f * amin;
        __syncthreads();
    }

    // ---------------- F = f(T) via Parlett recurrence ----------------
    for (int idx = tid; idx < N * N; idx += 64) {
        int i = idx >> 6, j = idx & 63;
        F[i * LDH + j] = (i == j) ? make_float2(s_v[i], 0.f) : make_float2(0.f, 0.f);
    }
    __syncthreads();
    for (int p = 1; p < N; p++) {
        int i = tid;
        if (i + p < N) {
            int j = i + p;
            float2 num = cmul(H[i * LDH + j], csub(F[i * LDH + i], F[j * LDH + j]));
            for (int kk = i + 1; kk < j; kk++) {
                float2 t1 = cmul(F[i * LDH + kk], H[kk * LDH + j]);
                float2 t2 = cmul(H[i * LDH + kk], F[kk * LDH + j]);
                num = cadd(num, csub(t1, t2));
            }
            float2 den = csub(H[i * LDH + i], H[j * LDH + j]);
            float dd = fmaxf(cabs2f(den), 1e-30f);
            // num / den = num * conj(den) / |den|^2
            F[i * LDH + j] = make_float2((num.x * den.x + num.y * den.y) / dd,
                                         (num.y * den.x - num.x * den.y) / dd);
        }
        __syncthreads();
    }

    // ---------------- G = Q * F  (into H; row per thread) ----------------
    {
        int i = tid;
        for (int j = 0; j < N; j++) {
            float2 acc = make_float2(0.f, 0.f);
            // F is upper triangular: k <= j
            for (int kk = 0; kk <= j; kk++) {
                float2 q = Q[i * LDH + kk], fv = F[kk * LDH + j];
                acc.x += q.x * fv.x - q.y * fv.y;
                acc.y += q.x * fv.y + q.y * fv.x;
            }
            H[i * LDH + j] = acc;
        }
    }
    __syncthreads();

    // ---------------- Re(M) = Re(G * Q^H) into F.x ----------------
    {
        int i = tid;
        for (int j = 0; j < N; j++) {
            float acc = 0.f;
            for (int kk = 0; kk < N; kk++) {
                float2 gv = H[i * LDH + kk], qv = Q[j * LDH + kk];
                acc += gv.x * qv.x + gv.y * qv.y;   // Re(g * conj(q))
            }
            F[i * LDH + j].x = acc;
        }
    }
    __syncthreads();

    // ---------------- out = 0.5*(Re(M) + Re(M)^T) ----------------
    for (int idx = tid; idx < N * N; idx += 64) {
        int i = idx >> 6, j = idx & 63;
        Og[idx] = 0.5f * (F[i * LDH + j].x + F[j * LDH + i].x);
    }
}

extern "C" void kernel_launch(void* const* d_in, const int* in_sizes, int n_in,
                              void* d_out, int out_size) {
    const float* x = (const float*)d_in[0];
    float* out = (float*)d_out;
    int nmat = in_sizes[0] / (N * N);
    size_t smem = 3 * N * LDH * sizeof(float2);  // 99,840 bytes
    cudaFuncSetAttribute(spd_project_kernel,
                         cudaFuncAttributeMaxDynamicSharedMemorySize, (int)smem);
    spd_project_kernel<<<nmat, 64, smem>>>(x, out, nmat);
}

// round 6
// speedup vs baseline: 1.6509x; 1.6509x over previous
#include <cuda_runtime.h>
#include <math.h>

// Batched SPD projection: per 64x64 real matrix A,
//   A = Q T Q^H (Hessenberg + complex single-shift QR, fused 1-barrier chase),
//   F = f(T) by Parlett (F packed into lower triangle of H),
//   M = Q F Q^H,  out = 0.5*(Re(M) + Re(M)^T).

#define N 64
#define LDH 65
#define ULPF 1.1920929e-7f
#define MAXSWEEPS 1920

__device__ __forceinline__ float2 cadd(float2 a, float2 b){ return make_float2(a.x+b.x, a.y+b.y); }
__device__ __forceinline__ float2 csub(float2 a, float2 b){ return make_float2(a.x-b.x, a.y-b.y); }
__device__ __forceinline__ float2 cmulc(float2 a, float2 b){ return make_float2(a.x*b.x-a.y*b.y, a.x*b.y+a.y*b.x); }
__device__ __forceinline__ float cabs1(float2 a){ return fabsf(a.x)+fabsf(a.y); }
__device__ __forceinline__ float cabs2f(float2 a){ return a.x*a.x+a.y*a.y; }

// left Givens on (row k, row k+1):  a' = c*a + s*b ; b' = c*b - conj(s)*a
__device__ __forceinline__ void rotL(float2& a, float2& b, float c, float2 s){
    float2 na = make_float2(c*a.x + s.x*b.x - s.y*b.y, c*a.y + s.x*b.y + s.y*b.x);
    float2 nb = make_float2(c*b.x - (s.x*a.x + s.y*a.y), c*b.y - (s.x*a.y - s.y*a.x));
    a = na; b = nb;
}
// right Givens on (col k, col k+1): a' = c*a + conj(s)*b ; b' = c*b - s*a
__device__ __forceinline__ void rotR(float2& a, float2& b, float c, float2 s){
    float2 na = make_float2(c*a.x + s.x*b.x + s.y*b.y, c*a.y + s.x*b.y - s.y*b.x);
    float2 nb = make_float2(c*b.x - (s.x*a.x - s.y*a.y), c*b.y - (s.x*a.y + s.y*a.x));
    a = na; b = nb;
}

__global__ void __launch_bounds__(64, 3)
spd_project_kernel(const float* __restrict__ X, float* __restrict__ OUT, int nmat)
{
    extern __shared__ float2 sm[];
    float2* H = sm;              // Hessenberg -> T (upper) ; F packed in strict lower ; later G ; later Re(M) in .x
    float2* Q = sm + N * LDH;    // accumulated similarity

    __shared__ float  s_red[2];
    __shared__ float  s_v[N];
    __shared__ float  s_fd[N];        // diag of F (real)
    __shared__ float2 s_mbox[2][2];   // double-buffered (f, g) mailbox for chase

    const int tid = threadIdx.x;
    const int g = blockIdx.x;
    if (g >= nmat) return;
    const float* A = X + (size_t)g * (N * N);
    float* Og = OUT + (size_t)g * (N * N);

    // ---------------- load A, Q = I ----------------
    for (int idx = tid; idx < N * N; idx += 64) {
        int i = idx >> 6, j = idx & 63;
        H[i * LDH + j] = make_float2(A[idx], 0.f);
        Q[i * LDH + j] = make_float2((i == j) ? 1.f : 0.f, 0.f);
    }
    __syncthreads();

    // ---------------- Hessenberg reduction (real; .y stays 0) ----------------
    for (int k = 0; k < N - 2; k++) {
        const int m = N - 1 - k;
        float t = 0.f;
        { int row = k + 2 + tid; if (row < N) { float h = H[row * LDH + k].x; t = h * h; } }
        #pragma unroll
        for (int off = 16; off >= 1; off >>= 1) t += __shfl_xor_sync(0xffffffffu, t, off);
        if ((tid & 31) == 0) s_red[tid >> 5] = t;
        __syncthreads();
        const float sigma = s_red[0] + s_red[1];
        if (sigma > 0.f) {   // uniform across threads
            float x0 = H[(k + 1) * LDH + k].x;
            float mu = sqrtf(x0 * x0 + sigma);
            float v0 = (x0 <= 0.f) ? (x0 - mu) : (-sigma / (x0 + mu));
            float beta = 2.f * v0 * v0 / (sigma + v0 * v0);
            float inv_v0 = 1.f / v0;
            if (tid < m) s_v[tid] = (tid == 0) ? 1.f : H[(k + 1 + tid) * LDH + k].x * inv_v0;
            __syncthreads();
            // left: one column per thread
            { int j = k + tid;
              if (j < N) {
                  float w = 0.f;
                  for (int i = 0; i < m; i++) w += s_v[i] * H[(k + 1 + i) * LDH + j].x;
                  w *= beta;
                  for (int i = 0; i < m; i++) H[(k + 1 + i) * LDH + j].x -= s_v[i] * w;
              } }
            __syncthreads();
            // right on H and Q, one row per thread; fold in exact-zero cleanup
            { int i = tid;
              float w = 0.f, wq = 0.f;
              for (int l = 0; l < m; l++) w += H[i * LDH + k + 1 + l].x * s_v[l];
              w *= beta;
              for (int l = 0; l < m; l++) H[i * LDH + k + 1 + l].x -= w * s_v[l];
              for (int l = 0; l < m; l++) wq += Q[i * LDH + k + 1 + l].x * s_v[l];
              wq *= beta;
              for (int l = 0; l < m; l++) Q[i * LDH + k + 1 + l].x -= wq * s_v[l];
              if (i >= k + 2) H[i * LDH + k].x = 0.f;
            }
            __syncthreads();
        } else {
            __syncthreads();  // protect s_red reuse next iteration
        }
    }

    // ---------------- complex single-shift QR; all control redundant on all threads ----------------
    int its = 0, totit = 0, hi = N - 1;
    while (true) {
        // deflation scan (redundant; benign same-value write races)
        while (hi > 0) {
            float sub = cabs1(H[hi * LDH + hi - 1]);
            float dd = cabs1(H[(hi - 1) * LDH + hi - 1]) + cabs1(H[hi * LDH + hi]);
            if (sub <= ULPF * dd + 1e-30f) {
                H[hi * LDH + hi - 1] = make_float2(0.f, 0.f);
                hi--; its = 0;
            } else break;
        }
        if (hi == 0 || totit >= MAXSWEEPS) break;
        totit++; its++;
        int lo = hi;
        while (lo > 0) {
            float sub = cabs1(H[lo * LDH + lo - 1]);
            float dd = cabs1(H[(lo - 1) * LDH + lo - 1]) + cabs1(H[lo * LDH + lo]);
            if (sub <= ULPF * dd + 1e-30f) {
                H[lo * LDH + lo - 1] = make_float2(0.f, 0.f);
                break;
            }
            lo--;
        }
        float2 sig;
        if ((its % 10) == 0) {   // exceptional shift
            sig = H[hi * LDH + hi];
            sig.x += 0.75f * cabs1(H[hi * LDH + hi - 1]);
        } else {                 // Wilkinson shift from trailing 2x2
            float2 a = H[(hi - 1) * LDH + hi - 1], b = H[(hi - 1) * LDH + hi];
            float2 cc = H[hi * LDH + hi - 1],      d2 = H[hi * LDH + hi];
            float2 tr = make_float2(0.5f * (a.x + d2.x), 0.5f * (a.y + d2.y));
            float2 u = make_float2(0.5f * (a.x - d2.x), 0.5f * (a.y - d2.y));
            float2 disc = cadd(cmulc(u, u), cmulc(b, cc));
            float mm = sqrtf(disc.x * disc.x + disc.y * disc.y);
            float re = sqrtf(fmaxf(0.5f * (mm + disc.x), 0.f));
            float im = sqrtf(fmaxf(0.5f * (mm - disc.x), 0.f));
            im = copysignf(im, disc.y);
            float2 sq = make_float2(re, im);
            float2 e1 = cadd(tr, sq), e2 = csub(tr, sq);
            sig = (cabs2f(csub(e1, d2)) < cabs2f(csub(e2, d2))) ? e1 : e2;
        }

        // bulge chase: 1 barrier per step (+1 at k==lo)
        for (int k = lo; k < hi; k++) {
            float2 f, gg;
            if (k == lo) { f = csub(H[lo * LDH + lo], sig); gg = H[(lo + 1) * LDH + lo]; }
            else         { f = s_mbox[k & 1][0];            gg = s_mbox[k & 1][1]; }
            float ag = cabs2f(gg), af = cabs2f(f);
            float c; float2 s, r;
            if (ag == 0.f) {
                c = 1.f; s = make_float2(0.f, 0.f); r = f;
            } else if (af == 0.f) {
                float gn = sqrtf(ag); float gi = 1.f / gn;
                c = 0.f; s = make_float2(gg.x * gi, -gg.y * gi); r = make_float2(gn, 0.f);
            } else {
                float irf = rsqrtf(af), ird = rsqrtf(af + ag);
                float fa = af * irf;                 // sqrt(af)
                c = fa * ird;
                float sc = irf * ird;
                s = make_float2((f.x * gg.x + f.y * gg.y) * sc,
                                (f.y * gg.x - f.x * gg.y) * sc);
                float rs = (af + ag) * ird * irf;    // sqrt(af+ag)/sqrt(af)
                r = make_float2(f.x * rs, f.y * rs);
            }
            if (k == lo) __syncthreads();  // first step reads f,gg from smem that corner will overwrite

            // ---- disjoint parallel applies ----
            if (tid >= 1) {                       // left: cols k+2..N-1, rows k,k+1
                int j = k + 1 + tid;
                if (j < N) {
                    float2 a = H[k * LDH + j], b = H[(k + 1) * LDH + j];
                    rotL(a, b, c, s);
                    H[k * LDH + j] = a; H[(k + 1) * LDH + j] = b;
                }
            }
            if (tid < k) {                        // right: rows 0..k-1, cols k,k+1
                float2 a = H[tid * LDH + k], b = H[tid * LDH + k + 1];
                rotR(a, b, c, s);
                H[tid * LDH + k] = a; H[tid * LDH + k + 1] = b;
            }
            {                                     // Q right: every row
                float2 a = Q[tid * LDH + k], b = Q[tid * LDH + k + 1];
                rotR(a, b, c, s);
                Q[tid * LDH + k] = a; Q[tid * LDH + k + 1] = b;
            }
            if (tid == 63) {                      // corner: 2x2 both-sided + bulge row + mailbox
                if (k > lo) H[k * LDH + k - 1] = r;
                float2 p00 = H[k * LDH + k],       p01 = H[k * LDH + k + 1];
                float2 p10 = H[(k + 1) * LDH + k], p11 = H[(k + 1) * LDH + k + 1];
                rotL(p00, p10, c, s);   // col k
                rotL(p01, p11, c, s);   // col k+1
                rotR(p00, p01, c, s);   // row k
                rotR(p10, p11, c, s);   // row k+1 -> p10 = next f
                H[k * LDH + k] = p00;       H[k * LDH + k + 1] = p01;
                H[(k + 1) * LDH + k] = p10; H[(k + 1) * LDH + k + 1] = p11;
                float2 ggn = make_float2(0.f, 0.f);
                if (k + 2 <= hi) {
                    float2 b2 = H[(k + 2) * LDH + k + 1];
                    ggn = make_float2(s.x * b2.x + s.y * b2.y, s.x * b2.y - s.y * b2.x); // conj(s)*b2
                    H[(k + 2) * LDH + k] = ggn;                 // bulge (old value structurally 0)
                    H[(k + 2) * LDH + k + 1] = make_float2(c * b2.x, c * b2.y);
                }
                s_mbox[(k + 1) & 1][0] = p10;
                s_mbox[(k + 1) & 1][1] = ggn;
            }
            __syncthreads();
        }
    }
    __syncthreads();

    // ---------------- lam = |w| + eps*min|w| ----------------
    {
        float2 w = H[tid * LDH + tid];
        float a = sqrtf(cabs2f(w));
        float t = a;
        #pragma unroll
        for (int off = 16; off >= 1; off >>= 1) t = fminf(t, __shfl_xor_sync(0xffffffffu, t, off));
        if ((tid & 31) == 0) s_red[tid >> 5] = t;
        __syncthreads();
        float amin = fminf(s_red[0], s_red[1]);
        s_fd[tid] = a + 1e-6f * amin;
        __syncthreads();
    }

    // ---------------- F = f(T) via Parlett; F[i][j] (i<j) stored at H[j][i] ----------------
    for (int p = 1; p < N; p++) {
        int i = tid, j = i + p;
        if (j < N) {
            float2 Tij = H[i * LDH + j];
            float fdiff = s_fd[i] - s_fd[j];
            float2 num = make_float2(Tij.x * fdiff, Tij.y * fdiff);
            for (int kk = i + 1; kk < j; kk++) {
                float2 Fik = H[kk * LDH + i];   // F[i][kk] packed
                float2 Tkj = H[kk * LDH + j];
                float2 Tik = H[i * LDH + kk];
                float2 Fkj = H[j * LDH + kk];   // F[kk][j] packed
                num.x += (Fik.x * Tkj.x - Fik.y * Tkj.y) - (Tik.x * Fkj.x - Tik.y * Fkj.y);
                num.y += (Fik.x * Tkj.y + Fik.y * Tkj.x) - (Tik.x * Fkj.y + Tik.y * Fkj.x);
            }
            float2 den = csub(H[i * LDH + i], H[j * LDH + j]);
            float dd = fmaxf(cabs2f(den), 1e-30f);
            H[j * LDH + i] = make_float2((num.x * den.x + num.y * den.y) / dd,
                                         (num.y * den.x - num.x * den.y) / dd);
        }
        __syncthreads();
    }

    // ---------------- G = Q * F  (stage row in registers, then overwrite H) ----------------
    {
        float2 acc[N];
        const int i = tid;
        for (int j = 0; j < N; j++) {
            float2 qd = Q[i * LDH + j];
            float2 a = make_float2(qd.x * s_fd[j], qd.y * s_fd[j]);
            for (int kk = 0; kk < j; kk++) {
                float2 qv = Q[i * LDH + kk];
                float2 fv = H[j * LDH + kk];   // F[kk][j] packed
                a.x += qv.x * fv.x - qv.y * fv.y;
                a.y += qv.x * fv.y + qv.y * fv.x;
            }
            acc[j] = a;
        }
        __syncthreads();  // all F reads complete before any overwrite
        for (int j = 0; j < N; j++) H[i * LDH + j] = acc[j];
    }
    __syncthreads();

    // ---------------- Re(M) = Re(G * Q^H) into H[i][*].x (own-row only) ----------------
    {
        float accr[N];
        const int i = tid;
        for (int j = 0; j < N; j++) {
            float a = 0.f;
            for (int kk = 0; kk < N; kk++) {
                float2 gv = H[i * LDH + kk], qv = Q[j * LDH + kk];
                a += gv.x * qv.x + gv.y * qv.y;   // Re(g * conj(q))
            }
            accr[j] = a;
        }
        for (int j = 0; j < N; j++) H[i * LDH + j].x = accr[j];
    }
    __syncthreads();

    // ---------------- out = 0.5*(Re(M) + Re(M)^T) ----------------
    for (int idx = tid; idx < N * N; idx += 64) {
        int i = idx >> 6, j = idx & 63;
        Og[idx] = 0.5f * (H[i * LDH + j].x + H[j * LDH + i].x);
    }
}

extern "C" void kernel_launch(void* const* d_in, const int* in_sizes, int n_in,
                              void* d_out, int out_size) {
    const float* x = (const float*)d_in[0];
    float* out = (float*)d_out;
    int nmat = in_sizes[0] / (N * N);
    size_t smem = 2 * N * LDH * sizeof(float2);  // 66,560 bytes -> 3 blocks/SM
    cudaFuncSetAttribute(spd_project_kernel,
                         cudaFuncAttributeMaxDynamicSharedMemorySize, (int)smem);
    spd_project_kernel<<<nmat, 64, smem>>>(x, out, nmat);
}